// round 1
// baseline (speedup 1.0000x reference)
#include <cuda_runtime.h>
#include <math.h>

#define EPSBN 1e-5f
#define BSZ 8
#define CIN 256
#define C2 128
#define HW 4096
#define HW4 1024

// ---------------- scratch (device globals; no runtime allocation) ----------------
__device__ float g_x1[(size_t)BSZ * HW * C2];      // conv1 out, NCHW flat == x1 [4096,128] rm
__device__ float g_c2[(size_t)BSZ * C2 * HW];      // conv2 out (pre-pool), NCHW
__device__ float g_p23[(size_t)BSZ * C2 * HW4];    // pooled: x2 [128,1024] rm == x3 [1024,128] rm
__device__ float g_S[(size_t)BSZ * HW * HW4];      // logits [4096,1024] per batch (134MB)
__device__ float g_rmax[BSZ * HW];
__device__ float g_rsum[BSZ * HW];
__device__ float g_O[(size_t)BSZ * HW * C2];       // attention out [4096,128] rm == NCHW [128,4096]

// ---------------- generic tiled GEMM: C = f(A[M,K] rm) * B[K,N] rm ----------------
// MODE 0: plain store
// MODE 1: BN+ReLU epilogue (per-row channel params)
// MODE 2: BN+ReLU + residual add
// MODE 3: A-transform exp(a - rowmax[m]); epilogue scale by 1/rowsum[m]
struct GemmArgs {
    const float* A; const float* B; float* C;
    int M, N, K;
    long long sAb, sBb, sCb;            // per-batch strides (elements)
    const float* bias; const float* g; const float* beta;
    const float* mean; const float* var;
    const float* res; long long sResB;
    const float* rowmax; const float* rowsum;
};

template <int MODE>
__global__ __launch_bounds__(256) void gemm_k(GemmArgs ga) {
    __shared__ float As[16][128];
    __shared__ float Bs[16][128];

    const int bz = blockIdx.z;
    const float* A = ga.A + (size_t)bz * ga.sAb;
    const float* Bp = ga.B + (size_t)bz * ga.sBb;
    float* C = ga.C + (size_t)bz * ga.sCb;

    const int mBase = blockIdx.y * 128;
    const int nBase = blockIdx.x * 128;
    const int tid = threadIdx.x;
    const int tx = tid & 15, ty = tid >> 4;
    const int N = ga.N, K = ga.K;

    const float* rmax = nullptr;
    if (MODE == 3) rmax = ga.rowmax + (size_t)bz * ga.M;

    float acc[8][8];
#pragma unroll
    for (int i = 0; i < 8; i++)
#pragma unroll
        for (int j = 0; j < 8; j++) acc[i][j] = 0.f;

    for (int k0 = 0; k0 < K; k0 += 16) {
        // A tile: 128 rows x 16 k, row-major stride K. 512 float4, 2 per thread.
#pragma unroll
        for (int i = 0; i < 2; i++) {
            int idx = tid + i * 256;
            int row = idx >> 2;
            int k4 = (idx & 3) << 2;
            float4 v = *(const float4*)(A + (size_t)(mBase + row) * K + k0 + k4);
            if (MODE == 3) {
                float rm = rmax[mBase + row];
                v.x = __expf(v.x - rm); v.y = __expf(v.y - rm);
                v.z = __expf(v.z - rm); v.w = __expf(v.w - rm);
            }
            As[k4 + 0][row] = v.x; As[k4 + 1][row] = v.y;
            As[k4 + 2][row] = v.z; As[k4 + 3][row] = v.w;
        }
        // B tile: 16 k-rows x 128 n, row-major stride N.
#pragma unroll
        for (int i = 0; i < 2; i++) {
            int idx = tid + i * 256;
            int kr = idx >> 5;
            int n4 = (idx & 31) << 2;
            *(float4*)&Bs[kr][n4] =
                *(const float4*)(Bp + (size_t)(k0 + kr) * N + nBase + n4);
        }
        __syncthreads();
#pragma unroll
        for (int k = 0; k < 16; k++) {
            float ar[8], br[8];
            *(float4*)&ar[0] = *(float4*)&As[k][ty * 8];
            *(float4*)&ar[4] = *(float4*)&As[k][ty * 8 + 4];
            *(float4*)&br[0] = *(float4*)&Bs[k][tx * 8];
            *(float4*)&br[4] = *(float4*)&Bs[k][tx * 8 + 4];
#pragma unroll
            for (int i = 0; i < 8; i++)
#pragma unroll
                for (int j = 0; j < 8; j++)
                    acc[i][j] = fmaf(ar[i], br[j], acc[i][j]);
        }
        __syncthreads();
    }

    // epilogue
#pragma unroll
    for (int i = 0; i < 8; i++) {
        int m = mBase + ty * 8 + i;
        float sc = 1.f, sh = 0.f, bi = 0.f, inv = 1.f;
        if (MODE == 1 || MODE == 2) {
            sc = ga.g[m] * rsqrtf(ga.var[m] + EPSBN);
            sh = ga.beta[m] - ga.mean[m] * sc;
            bi = ga.bias[m];
        }
        if (MODE == 3) inv = 1.0f / ga.rowsum[(size_t)bz * ga.M + m];
#pragma unroll
        for (int j = 0; j < 8; j += 4) {
            float4 v;
            float* pv = &v.x;
#pragma unroll
            for (int c = 0; c < 4; c++) {
                int n = nBase + tx * 8 + j + c;
                float val = acc[i][j + c];
                if (MODE == 1 || MODE == 2) {
                    val = (val + bi) * sc + sh;
                    val = fmaxf(val, 0.f);
                }
                if (MODE == 2)
                    val += ga.res[(size_t)bz * ga.sResB + (size_t)m * N + n];
                if (MODE == 3) val *= inv;
                pv[c] = val;
            }
            *(float4*)(C + (size_t)m * N + nBase + tx * 8 + j) = v;
        }
    }
}

// ---------------- maxpool 3x3 s2 p1 : [B*C2,64,64] -> [B*C2,32,32] ----------------
__global__ __launch_bounds__(256) void maxpool_k(const float* __restrict__ in,
                                                 float* __restrict__ out) {
    int idx = blockIdx.x * blockDim.x + threadIdx.x;
    if (idx >= BSZ * C2 * 1024) return;
    int ow = idx & 31, oh = (idx >> 5) & 31, ch = idx >> 10;
    const float* p = in + (size_t)ch * 4096;
    int h0 = oh * 2 - 1, w0 = ow * 2 - 1;
    float m = -INFINITY;
#pragma unroll
    for (int dh = 0; dh < 3; dh++) {
        int h = h0 + dh;
        if (h < 0 || h >= 64) continue;
#pragma unroll
        for (int dw = 0; dw < 3; dw++) {
            int w = w0 + dw;
            if (w < 0 || w >= 64) continue;
            m = fmaxf(m, p[h * 64 + w]);
        }
    }
    out[idx] = m;
}

// ---------------- per-row max & sum(exp(x-max)) over 1024-wide rows ----------------
__global__ __launch_bounds__(256) void stats_k(const float* __restrict__ S,
                                               float* __restrict__ rmax,
                                               float* __restrict__ rsum) {
    int warp = (blockIdx.x * blockDim.x + threadIdx.x) >> 5;
    int lane = threadIdx.x & 31;
    if (warp >= BSZ * HW) return;
    const float* row = S + (size_t)warp * 1024;
    float v[32];
    float mx = -INFINITY;
#pragma unroll
    for (int i = 0; i < 32; i++) {
        v[i] = row[lane + i * 32];
        mx = fmaxf(mx, v[i]);
    }
#pragma unroll
    for (int o = 16; o > 0; o >>= 1)
        mx = fmaxf(mx, __shfl_xor_sync(0xffffffffu, mx, o));
    float s = 0.f;
#pragma unroll
    for (int i = 0; i < 32; i++) s += __expf(v[i] - mx);
#pragma unroll
    for (int o = 16; o > 0; o >>= 1)
        s += __shfl_xor_sync(0xffffffffu, s, o);
    if (lane == 0) {
        rmax[warp] = mx;
        rsum[warp] = s;
    }
}

// ---------------- launcher ----------------
extern "C" void kernel_launch(void* const* d_in, const int* in_sizes, int n_in,
                              void* d_out, int out_size) {
    const float* a       = (const float*)d_in[0];
    const float* conv1_w = (const float*)d_in[1];
    const float* conv1_b = (const float*)d_in[2];
    const float* bn1_g   = (const float*)d_in[3];
    const float* bn1_b   = (const float*)d_in[4];
    const float* bn1_m   = (const float*)d_in[5];
    const float* bn1_v   = (const float*)d_in[6];
    const float* conv2_w = (const float*)d_in[7];
    const float* conv2_b = (const float*)d_in[8];
    const float* bn2_g   = (const float*)d_in[9];
    const float* bn2_b   = (const float*)d_in[10];
    const float* bn2_m   = (const float*)d_in[11];
    const float* bn2_v   = (const float*)d_in[12];
    const float* conv3_w = (const float*)d_in[13];
    const float* conv3_b = (const float*)d_in[14];
    const float* bn3_g   = (const float*)d_in[15];
    const float* bn3_b   = (const float*)d_in[16];
    const float* bn3_m   = (const float*)d_in[17];
    const float* bn3_v   = (const float*)d_in[18];
    float* out = (float*)d_out;

    float *px1, *pc2, *pp, *pS, *prm, *prs, *pO;
    cudaGetSymbolAddress((void**)&px1, g_x1);
    cudaGetSymbolAddress((void**)&pc2, g_c2);
    cudaGetSymbolAddress((void**)&pp, g_p23);
    cudaGetSymbolAddress((void**)&pS, g_S);
    cudaGetSymbolAddress((void**)&prm, g_rmax);
    cudaGetSymbolAddress((void**)&prs, g_rsum);
    cudaGetSymbolAddress((void**)&pO, g_O);

    GemmArgs ga;

    // K1: x1 = BN(ReLU(conv1(a)))  ->  [B,128,4096] NCHW flat
    ga = {};
    ga.A = conv1_w; ga.B = a; ga.C = px1;
    ga.M = C2; ga.N = HW; ga.K = CIN;
    ga.sAb = 0; ga.sBb = (long long)CIN * HW; ga.sCb = (long long)C2 * HW;
    ga.bias = conv1_b; ga.g = bn1_g; ga.beta = bn1_b; ga.mean = bn1_m; ga.var = bn1_v;
    gemm_k<1><<<dim3(HW / 128, C2 / 128, BSZ), 256>>>(ga);

    // K2: conv2 branch (pre-pool)
    ga = {};
    ga.A = conv2_w; ga.B = a; ga.C = pc2;
    ga.M = C2; ga.N = HW; ga.K = CIN;
    ga.sAb = 0; ga.sBb = (long long)CIN * HW; ga.sCb = (long long)C2 * HW;
    ga.bias = conv2_b; ga.g = bn2_g; ga.beta = bn2_b; ga.mean = bn2_m; ga.var = bn2_v;
    gemm_k<1><<<dim3(HW / 128, C2 / 128, BSZ), 256>>>(ga);

    // K3: maxpool -> pooled buffer (x2/x3 views)
    maxpool_k<<<(BSZ * C2 * 1024 + 255) / 256, 256>>>(pc2, pp);

    // K4: S = x1 @ x2   (M=4096, N=1024, K=128)
    ga = {};
    ga.A = px1; ga.B = pp; ga.C = pS;
    ga.M = HW; ga.N = HW4; ga.K = C2;
    ga.sAb = (long long)HW * C2; ga.sBb = (long long)C2 * HW4;
    ga.sCb = (long long)HW * HW4;
    gemm_k<0><<<dim3(HW4 / 128, HW / 128, BSZ), 256>>>(ga);

    // K5: row softmax stats
    stats_k<<<(BSZ * HW) / 8, 256>>>(pS, prm, prs);

    // K6: O = softmax(S) @ x3   (M=4096, N=128, K=1024)
    ga = {};
    ga.A = pS; ga.B = pp; ga.C = pO;
    ga.M = HW; ga.N = C2; ga.K = HW4;
    ga.sAb = (long long)HW * HW4; ga.sBb = (long long)C2 * HW4;
    ga.sCb = (long long)HW * C2;
    ga.rowmax = prm; ga.rowsum = prs;
    gemm_k<3><<<dim3(C2 / 128, HW / 128, BSZ), 256>>>(ga);

    // K7: out = ReLU(BN(conv3(O))) + a   (M=256, N=4096, K=128)
    ga = {};
    ga.A = conv3_w; ga.B = pO; ga.C = out;
    ga.M = CIN; ga.N = HW; ga.K = C2;
    ga.sAb = 0; ga.sBb = (long long)C2 * HW; ga.sCb = (long long)CIN * HW;
    ga.bias = conv3_b; ga.g = bn3_g; ga.beta = bn3_b; ga.mean = bn3_m; ga.var = bn3_v;
    ga.res = a; ga.sResB = (long long)CIN * HW;
    gemm_k<2><<<dim3(HW / 128, CIN / 128, BSZ), 256>>>(ga);
}